// round 3
// baseline (speedup 1.0000x reference)
#include <cuda_runtime.h>
#include <cuda_bf16.h>
#include <math.h>

#define BB 32
#define CC 256
#define OO 256
#define HH 56
#define WW 56
#define CHK 4
#define HWSZ (HH*WW)          // 3136
#define CB 4                  // c-channels per pipeline stage
#define NSTG (CC/CB)          // 64 stages
#define WPAD 10               // padded floats per 3x3 filter in g_dynw / smem

// ---- scratch (module-load allocated; allowed) ----
__device__ float g_pooled[BB*CC];                       // [B][C]
__device__ float g_kern[BB*CC*CHK];                     // [B][C][4]
__device__ float g_dynw[(size_t)BB*CC*OO*WPAD];         // [B][C][O][10] ~83.9MB

__device__ __forceinline__ unsigned smem_u32(const void* p) {
    return (unsigned)__cvta_generic_to_shared(p);
}
__device__ __forceinline__ void cp_async16(unsigned dst, const void* src) {
    asm volatile("cp.async.cg.shared.global [%0], [%1], 16;" :: "r"(dst), "l"(src));
}
__device__ __forceinline__ void cp_async4_z(unsigned dst, const void* src, int src_sz) {
    asm volatile("cp.async.ca.shared.global [%0], [%1], 4, %2;" :: "r"(dst), "l"(src), "r"(src_sz));
}

// ---------------------------------------------------------------
// Kernel 1: global average pool. one block per (b,c)
// ---------------------------------------------------------------
__global__ void pool_kernel(const float* __restrict__ x) {
    __shared__ float red[256];
    int bc = blockIdx.x;
    const float* p = x + (size_t)bc * HWSZ;
    float s = 0.f;
    for (int i = threadIdx.x; i < HWSZ; i += 256) s += p[i];
    red[threadIdx.x] = s;
    __syncthreads();
    for (int off = 128; off > 0; off >>= 1) {
        if (threadIdx.x < off) red[threadIdx.x] += red[threadIdx.x + off];
        __syncthreads();
    }
    if (threadIdx.x == 0) g_pooled[bc] = red[0] * (1.0f / (float)HWSZ);
}

// ---------------------------------------------------------------
// Kernel 2: h = relu(pooled @ fc1^T); kern = h @ fc2^T + b. one block per b
// ---------------------------------------------------------------
__global__ void fc_kernel(const float* __restrict__ fc1,
                          const float* __restrict__ fc2,
                          const float* __restrict__ fc2b) {
    __shared__ float ps[CC];
    __shared__ float hs[CC];
    int b = blockIdx.x, tid = threadIdx.x;
    ps[tid] = g_pooled[b*CC + tid];
    __syncthreads();
    {
        const float* r1 = fc1 + (size_t)tid * CC;
        float a = 0.f;
        #pragma unroll 8
        for (int j = 0; j < CC; j++) a = fmaf(ps[j], r1[j], a);
        hs[tid] = fmaxf(a, 0.f);
    }
    __syncthreads();
    #pragma unroll
    for (int m4 = 0; m4 < 4; m4++) {
        int m = m4*CC + tid;                        // 0..1023 = c*4 + t
        const float* r2 = fc2 + (size_t)m * CC;
        float s = fc2b[m];
        #pragma unroll 8
        for (int j = 0; j < CC; j++) s = fmaf(hs[j], r2[j], s);
        g_kern[b*CC*CHK + m] = s;
    }
}

// ---------------------------------------------------------------
// Kernel 3: dyn_w[b][c][o][k] = sigmoid(sum_t kern[b,c,t]*cog[o,t,k]) * weight[o,c,k]
// padded to WPAD=10 floats per filter (k==9 -> 0) for aligned smem loads later.
// ---------------------------------------------------------------
__global__ void dynw_kernel(const float* __restrict__ cog,
                            const float* __restrict__ weight) {
    size_t idx = (size_t)blockIdx.x * 256 + threadIdx.x;
    const size_t total = (size_t)BB*CC*OO*WPAD;
    if (idx >= total) return;
    int k10 = (int)(idx % WPAD);
    size_t r = idx / WPAD;
    int o = (int)(r % OO); r /= OO;
    int c = (int)(r % CC);
    int b = (int)(r / CC);

    float outv = 0.f;
    if (k10 < 9) {
        const float4 kv = *(const float4*)(g_kern + ((size_t)b*CC + c)*4);
        const float* cg = cog + (size_t)o*36 + k10;
        float s = kv.x*cg[0] + kv.y*cg[9] + kv.z*cg[18] + kv.w*cg[27];
        float wv = weight[((size_t)o*CC + c)*9 + k10];
        outv = wv / (1.0f + __expf(-s));
    }
    g_dynw[idx] = outv;
}

// ---------------------------------------------------------------
// Kernel 4: per-sample conv, cp.async double-buffered.
// Block: b = blockIdx.z, og = blockIdx.y (128 o), tile = blockIdx.x (7x7 of 8x8 px)
// 256 threads: warp = spatial slot (2x4 px), lane = o-lane; thread: 4 o x 2x4 px.
// ---------------------------------------------------------------
__global__ __launch_bounds__(256, 2)
void conv_kernel(const float* __restrict__ x, float* __restrict__ out) {
    __shared__ __align__(16) float ws[2][CB][128*WPAD];   // 40960 B
    __shared__ __align__(16) float xs[2][CB][10][12];     //  3840 B

    const int tid  = threadIdx.x;
    const int otid = tid & 31;
    const int stid = tid >> 5;
    const int th = blockIdx.x / 7, tw = blockIdx.x % 7;
    const int og = blockIdx.y;
    const int b  = blockIdx.z;
    const int sh = (stid >> 1) * 2;
    const int sw = (stid & 1) * 4;
    const int h0 = th * 8, w0 = tw * 8;

    float acc[4][2][4];
    #pragma unroll
    for (int a = 0; a < 4; a++)
        #pragma unroll
        for (int dy = 0; dy < 2; dy++)
            #pragma unroll
            for (int dx = 0; dx < 4; dx++) acc[a][dy][dx] = 0.f;

    const float* xb = x + (size_t)b * CC * HWSZ;
    const float* wb = g_dynw + ((size_t)b * CC * OO + (size_t)og * 128) * WPAD;
    // per-c weight slab for this block: 128*WPAD = 1280 contiguous floats at wb + c*OO*WPAD

    // --- x-load decode (2 elements per thread, e = tid, tid+256 < 400) ---
    // element e: cb=e/100, r=(e%100)/10, col=e%10
    int xe0 = tid, xe1 = tid + 256;

    // ---- stage load helper (lambda-free, macro-ish via inline) ----
    #define ISSUE_STAGE(S, BUF)                                                        \
    {                                                                                  \
        const int c0_ = (S) * CB;                                                      \
        _Pragma("unroll")                                                              \
        for (int i = 0; i < 5; i++) {                                                  \
            int chunk = tid + i * 256;            /* 0..1279 */                        \
            int cb_ = chunk / 320;                                                     \
            int cc_ = chunk - cb_ * 320;          /* 16B chunk within c */             \
            const float* src = wb + (size_t)(c0_ + cb_) * (OO*WPAD) + cc_ * 4;         \
            cp_async16(smem_u32(&ws[BUF][cb_][cc_ * 4]), src);                         \
        }                                                                              \
        _Pragma("unroll")                                                              \
        for (int q = 0; q < 2; q++) {                                                  \
            int e = q ? xe1 : xe0;                                                     \
            if (e < CB * 100) {                                                        \
                int cb_ = e / 100;                                                     \
                int rr_ = (e - cb_ * 100) / 10;                                        \
                int c2_ = e % 10;                                                      \
                int gh_ = h0 - 1 + rr_;                                                \
                int gw_ = w0 - 1 + c2_;                                                \
                bool ok = (gh_ >= 0) && (gh_ < HH) && (gw_ >= 0) && (gw_ < WW);        \
                const float* src = ok ? (xb + ((size_t)(c0_ + cb_) * HH + gh_) * WW + gw_) : xb; \
                cp_async4_z(smem_u32(&xs[BUF][cb_][rr_][c2_]), src, ok ? 4 : 0);       \
            }                                                                          \
        }                                                                              \
    }

    // prologue: stage 0 into buf 0
    ISSUE_STAGE(0, 0);
    asm volatile("cp.async.commit_group;");

    for (int s = 0; s < NSTG; s++) {
        const int cur = s & 1;
        if (s + 1 < NSTG) ISSUE_STAGE(s + 1, cur ^ 1);
        asm volatile("cp.async.commit_group;");
        asm volatile("cp.async.wait_group 1;");
        __syncthreads();

        #pragma unroll
        for (int cb = 0; cb < CB; cb++) {
            float xr[4][6];
            #pragma unroll
            for (int r = 0; r < 4; r++) {
                float4 v4 = *(const float4*)&xs[cur][cb][sh + r][sw];
                float2 v2 = *(const float2*)&xs[cur][cb][sh + r][sw + 4];
                xr[r][0] = v4.x; xr[r][1] = v4.y; xr[r][2] = v4.z; xr[r][3] = v4.w;
                xr[r][4] = v2.x; xr[r][5] = v2.y;
            }
            #pragma unroll
            for (int o4 = 0; o4 < 4; o4++) {
                const float* wp = &ws[cur][cb][(otid + o4 * 32) * WPAD];
                float2 a0 = *(const float2*)(wp + 0);
                float2 a1 = *(const float2*)(wp + 2);
                float2 a2 = *(const float2*)(wp + 4);
                float2 a3 = *(const float2*)(wp + 6);
                float w8  = wp[8];
                float wv[9] = {a0.x, a0.y, a1.x, a1.y, a2.x, a2.y, a3.x, a3.y, w8};
                #pragma unroll
                for (int i = 0; i < 3; i++) {
                    #pragma unroll
                    for (int j = 0; j < 3; j++) {
                        float wcur = wv[i * 3 + j];
                        #pragma unroll
                        for (int dy = 0; dy < 2; dy++)
                            #pragma unroll
                            for (int dx = 0; dx < 4; dx++)
                                acc[o4][dy][dx] = fmaf(wcur, xr[dy + i][dx + j], acc[o4][dy][dx]);
                    }
                }
            }
        }
        __syncthreads();
    }
    #undef ISSUE_STAGE

    // ---- store ----
    #pragma unroll
    for (int o4 = 0; o4 < 4; o4++) {
        int o = og * 128 + otid + o4 * 32;
        #pragma unroll
        for (int dy = 0; dy < 2; dy++) {
            int hh = h0 + sh + dy;
            int wcol = w0 + sw;
            float4 v = make_float4(acc[o4][dy][0], acc[o4][dy][1],
                                   acc[o4][dy][2], acc[o4][dy][3]);
            *(float4*)(out + (((size_t)b * OO + o) * HH + hh) * WW + wcol) = v;
        }
    }
}

// ---------------------------------------------------------------
extern "C" void kernel_launch(void* const* d_in, const int* in_sizes, int n_in,
                              void* d_out, int out_size) {
    const float* x      = (const float*)d_in[0];
    const float* fc1_w  = (const float*)d_in[1];
    const float* fc2_w  = (const float*)d_in[2];
    const float* fc2_b  = (const float*)d_in[3];
    const float* cog_w  = (const float*)d_in[4];
    const float* weight = (const float*)d_in[5];
    float* out = (float*)d_out;

    pool_kernel<<<BB*CC, 256>>>(x);
    fc_kernel<<<BB, 256>>>(fc1_w, fc2_w, fc2_b);
    {
        size_t total = (size_t)BB*CC*OO*WPAD;
        int blocks = (int)((total + 255) / 256);
        dynw_kernel<<<blocks, 256>>>(cog_w, weight);
    }
    {
        dim3 grid(49, 2, BB);
        conv_kernel<<<grid, 256>>>(x, out);
    }
}

// round 7
// speedup vs baseline: 2.0084x; 2.0084x over previous
#include <cuda_runtime.h>
#include <cuda_bf16.h>
#include <cstdint>
#include <cstddef>
#include <math.h>

#define BB 32
#define CC 256
#define OO 256
#define HH 56
#define WW 56
#define HWSZ 3136
#define KTOT 2304
#define KST 32
#define NSTG 72          // 2304 / 32
#define APAD 36          // 32 k + 4 pad (conflict-free fragment LDS)
#define A_FLOATS (128*APAD)   // 4608
#define B_FLOATS (112*APAD)   // 4032
#define A_CHUNKS ((A_FLOATS*4)/16)   // 1152 x 16B
#define SMEM_CONV (2*(A_FLOATS+B_FLOATS)*4)   // 69120 B

// ---- scratch ----
__device__ float g_pooled[BB*CC];
__device__ float g_kern[BB*CC*4];
__device__ unsigned g_wA[(size_t)BB*2*NSTG*A_FLOATS];   // tf32 A images, ~85MB

// ---- helpers ----
__device__ __forceinline__ unsigned smem_u32(const void* p) {
    return (unsigned)__cvta_generic_to_shared((void*)p);
}
__device__ __forceinline__ void cp_async16(unsigned dst, const void* src) {
    asm volatile("cp.async.cg.shared.global [%0], [%1], 16;" :: "r"(dst), "l"(src));
}
__device__ __forceinline__ unsigned to_tf32(float f) {
    unsigned u; asm("cvt.rna.tf32.f32 %0, %1;" : "=r"(u) : "f"(f)); return u;
}
#define STS128(a, r0, r1, r2, r3) asm volatile("st.shared.v4.b32 [%0], {%1,%2,%3,%4};" :: "r"(a), "r"(r0), "r"(r1), "r"(r2), "r"(r3) : "memory")

// ---------------------------------------------------------------
// Kernel 1: global average pool. one block per (b,c)
// ---------------------------------------------------------------
__global__ void pool_kernel(const float* __restrict__ x) {
    __shared__ float red[256];
    int bc = blockIdx.x;
    const float* p = x + (size_t)bc * HWSZ;
    float s = 0.f;
    for (int i = threadIdx.x; i < HWSZ; i += 256) s += p[i];
    red[threadIdx.x] = s;
    __syncthreads();
    for (int off = 128; off > 0; off >>= 1) {
        if (threadIdx.x < off) red[threadIdx.x] += red[threadIdx.x + off];
        __syncthreads();
    }
    if (threadIdx.x == 0) g_pooled[bc] = red[0] * (1.0f / (float)HWSZ);
}

// ---------------------------------------------------------------
// Kernel 2: FCs. one block per b
// ---------------------------------------------------------------
__global__ void fc_kernel(const float* __restrict__ fc1,
                          const float* __restrict__ fc2,
                          const float* __restrict__ fc2b) {
    __shared__ float ps[CC];
    __shared__ float hs[CC];
    int b = blockIdx.x, tid = threadIdx.x;
    ps[tid] = g_pooled[b*CC + tid];
    __syncthreads();
    {
        const float* r1 = fc1 + (size_t)tid * CC;
        float a = 0.f;
        #pragma unroll 8
        for (int j = 0; j < CC; j++) a = fmaf(ps[j], r1[j], a);
        hs[tid] = fmaxf(a, 0.f);
    }
    __syncthreads();
    #pragma unroll
    for (int m4 = 0; m4 < 4; m4++) {
        int m = m4*CC + tid;                        // m = c*4 + t
        const float* r2 = fc2 + (size_t)m * CC;
        float s = fc2b[m];
        #pragma unroll 8
        for (int j = 0; j < CC; j++) s = fmaf(hs[j], r2[j], s);
        g_kern[b*CC*4 + m] = s;
    }
}

// ---------------------------------------------------------------
// Kernel 3: build tf32 A images, stage-major with pad:
//   g_wA[(b*2+og)][s][o_local][kk(0..31)+pad4]
//   A[o][k] = sigmoid(sum_t kern[b,c,t]*cog[o,t,r9]) * weight[o,c,r9], k=c*9+r9
// ---------------------------------------------------------------
__global__ void dynw_kernel(const float* __restrict__ cog,
                            const float* __restrict__ weight) {
    size_t idx = (size_t)blockIdx.x * 256 + threadIdx.x;   // < 64*72*4096
    int kk = (int)(idx & 31);
    int o  = (int)((idx >> 5) & 127);
    int s  = (int)((idx >> 12) % NSTG);
    int img= (int)((idx >> 12) / NSTG);
    int og = img & 1, b = img >> 1;
    int o_g = og*128 + o;
    int k = s*KST + kk;
    int c = k / 9, r9 = k - c*9;

    const float4 kv = *(const float4*)(g_kern + ((size_t)b*CC + c)*4);
    const float* cg = cog + (size_t)o_g * 36;
    float sa = kv.x*cg[r9] + kv.y*cg[9+r9] + kv.z*cg[18+r9] + kv.w*cg[27+r9];
    float wv = weight[((size_t)o_g*CC + c)*9 + r9];
    float val = wv / (1.0f + __expf(-sa));
    g_wA[((size_t)(img*NSTG + s)*128 + o)*APAD + kk] = to_tf32(val);
}

// ---------------------------------------------------------------
// Kernel 4: TF32 mma.sync implicit-GEMM conv.
// Block (tile, og, b): D[128 o][112 px(2 rows x 56)] = A[128][2304] * B[112][2304]^T
// 8 warps = 4(M) x 2(N); warp tile 32 o x 56 px; mma m16n8k8.
// ---------------------------------------------------------------
__global__ __launch_bounds__(256, 2)
void conv_kernel(const float* __restrict__ x, float* __restrict__ out) {
    extern __shared__ __align__(16) float dsm[];
    float* As = dsm;                      // [2][A_FLOATS]
    float* Bs = dsm + 2*A_FLOATS;         // [2][B_FLOATS]

    const int tid  = threadIdx.x;
    const int lane = tid & 31;
    const int wid  = tid >> 5;
    const int warpM = wid & 3;
    const int warpN = wid >> 2;
    const int tile = blockIdx.x, og = blockIdx.y, b = blockIdx.z;
    const int h0 = tile * 2;

    const float* xb = x + (size_t)b * CC * HWSZ;
    const uint4* gA = (const uint4*)g_wA + (size_t)((b*2 + og) * NSTG) * A_CHUNKS;

    // B-build thread mapping (224 active): px = tid%112, half = tid/112
    const int pxid = tid % 112;
    const int half = tid / 112;
    const int rr = pxid / 56, cw = pxid % 56;
    const int ghb = h0 + rr - 1, gwb = cw - 1;
    const bool bact = (half < 2);
    const int kk0 = half * 16;

    float acc[2][7][4];
    #pragma unroll
    for (int m = 0; m < 2; m++)
        #pragma unroll
        for (int n = 0; n < 7; n++)
            #pragma unroll
            for (int q = 0; q < 4; q++) acc[m][n][q] = 0.f;

    const int aoff = (warpM*32 + (lane >> 2))*APAD + (lane & 3);
    const int boff = (warpN*56 + (lane >> 2))*APAD + (lane & 3);

    #define LOAD_A(S, BUF)                                                       \
    {                                                                            \
        const uint4* src_ = gA + (size_t)(S) * A_CHUNKS;                         \
        unsigned dst_ = smem_u32(As + (BUF) * A_FLOATS);                         \
        _Pragma("unroll")                                                        \
        for (int i_ = 0; i_ < 5; i_++) {                                         \
            int ch_ = tid + i_ * 256;                                            \
            if (ch_ < A_CHUNKS) cp_async16(dst_ + ch_*16, src_ + ch_);           \
        }                                                                        \
        asm volatile("cp.async.commit_group;");                                  \
    }

    #define BUILD_B(S, BUF)                                                      \
    if (bact) {                                                                  \
        unsigned base_ = smem_u32(Bs + (BUF)*B_FLOATS + pxid*APAD + kk0);        \
        _Pragma("unroll")                                                        \
        for (int g_ = 0; g_ < 4; g_++) {                                         \
            unsigned vv_[4];                                                     \
            _Pragma("unroll")                                                    \
            for (int u_ = 0; u_ < 4; u_++) {                                     \
                int kk_ = kk0 + g_*4 + u_;                                       \
                int k_ = (S)*KST + kk_;                                          \
                int c_ = k_ / 9, r9_ = k_ - c_*9;                                \
                int i3_ = r9_ / 3, j3_ = r9_ - i3_*3;                            \
                int gh_ = ghb + i3_, gw_ = gwb + j3_;                            \
                float v_ = 0.f;                                                  \
                if (gh_ >= 0 && gh_ < HH && gw_ >= 0 && gw_ < WW)                \
                    v_ = xb[(size_t)c_ * HWSZ + gh_ * WW + gw_];                 \
                vv_[u_] = to_tf32(v_);                                           \
            }                                                                    \
            STS128(base_ + g_*16, vv_[0], vv_[1], vv_[2], vv_[3]);               \
        }                                                                        \
    }

    // prologue
    LOAD_A(0, 0);
    BUILD_B(0, 0);
    asm volatile("cp.async.wait_group 0;");
    __syncthreads();

    for (int s = 0; s < NSTG; s++) {
        const int p = s & 1;
        if (s + 1 < NSTG) { LOAD_A(s + 1, p ^ 1); BUILD_B(s + 1, p ^ 1); }

        const unsigned* Ap = (const unsigned*)(As + p * A_FLOATS);
        const unsigned* Bp = (const unsigned*)(Bs + p * B_FLOATS);
        #pragma unroll
        for (int ks = 0; ks < 4; ks++) {
            unsigned af[2][4], bf[7][2];
            #pragma unroll
            for (int m = 0; m < 2; m++) {
                const unsigned* ap = Ap + aoff + m*16*APAD + ks*8;
                af[m][0] = ap[0];
                af[m][1] = ap[8*APAD];
                af[m][2] = ap[4];
                af[m][3] = ap[8*APAD + 4];
            }
            #pragma unroll
            for (int n = 0; n < 7; n++) {
                const unsigned* bp = Bp + boff + n*8*APAD + ks*8;
                bf[n][0] = bp[0];
                bf[n][1] = bp[4];
            }
            #pragma unroll
            for (int m = 0; m < 2; m++)
                #pragma unroll
                for (int n = 0; n < 7; n++)
                    asm volatile(
                        "mma.sync.aligned.m16n8k8.row.col.f32.tf32.tf32.f32 "
                        "{%0,%1,%2,%3}, {%4,%5,%6,%7}, {%8,%9}, {%0,%1,%2,%3};"
                        : "+f"(acc[m][n][0]), "+f"(acc[m][n][1]),
                          "+f"(acc[m][n][2]), "+f"(acc[m][n][3])
                        : "r"(af[m][0]), "r"(af[m][1]), "r"(af[m][2]), "r"(af[m][3]),
                          "r"(bf[n][0]), "r"(bf[n][1]));
        }
        asm volatile("cp.async.wait_group 0;");
        __syncthreads();
    }
    #undef LOAD_A
    #undef BUILD_B

    // ---- epilogue: fragments -> gmem (all px of a warp share one h row) ----
    const int h = h0 + warpN;
    const int wbase = (lane & 3) * 2;
    #pragma unroll
    for (int m = 0; m < 2; m++) {
        int o = og*128 + warpM*32 + m*16 + (lane >> 2);
        float* r0 = out + ((size_t)b*OO + o)*HWSZ + h*WW;
        float* r1 = out + ((size_t)b*OO + o + 8)*HWSZ + h*WW;
        #pragma unroll
        for (int n = 0; n < 7; n++) {
            int w = n*8 + wbase;
            *(float2*)(r0 + w) = make_float2(acc[m][n][0], acc[m][n][1]);
            *(float2*)(r1 + w) = make_float2(acc[m][n][2], acc[m][n][3]);
        }
    }
}

// ---------------------------------------------------------------
extern "C" void kernel_launch(void* const* d_in, const int* in_sizes, int n_in,
                              void* d_out, int out_size) {
    const float* x      = (const float*)d_in[0];
    const float* fc1_w  = (const float*)d_in[1];
    const float* fc2_w  = (const float*)d_in[2];
    const float* fc2_b  = (const float*)d_in[3];
    const float* cog_w  = (const float*)d_in[4];
    const float* weight = (const float*)d_in[5];
    float* out = (float*)d_out;

    cudaFuncSetAttribute(conv_kernel, cudaFuncAttributeMaxDynamicSharedMemorySize, SMEM_CONV);

    pool_kernel<<<BB*CC, 256>>>(x);
    fc_kernel<<<BB, 256>>>(fc1_w, fc2_w, fc2_b);
    {
        int blocks = BB*2*NSTG*4096/256;   // 73728
        dynw_kernel<<<blocks, 256>>>(cog_w, weight);
    }
    {
        dim3 grid(28, 2, BB);
        conv_kernel<<<grid, 256, SMEM_CONV>>>(x, out);
    }
}

// round 9
// speedup vs baseline: 2.0869x; 1.0391x over previous
#include <cuda_runtime.h>
#include <cuda_bf16.h>
#include <cstdint>
#include <cstddef>
#include <math.h>

#define BB 32
#define CC 256
#define OO 256
#define HH 56
#define WW 56
#define HWSZ 3136
#define KTOT 2304
#define KST 32
#define NSTG 72          // 2304 / 32
#define APAD 36          // 32 k + 4 pad (conflict-free fragment LDS)
#define A_FLOATS (128*APAD)   // 4608
#define B_FLOATS (112*APAD)   // 4032
#define A_CHUNKS ((A_FLOATS*4)/16)   // 1152 x 16B
#define SMEM_CONV (2*(A_FLOATS+B_FLOATS)*4)   // 69120 B

// ---- scratch ----
__device__ float g_pooled[BB*CC];
__device__ float g_kern[BB*CC*4];
__device__ unsigned g_wA[(size_t)BB*2*NSTG*A_FLOATS];   // tf32 A images, ~85MB

// ---- helpers ----
__device__ __forceinline__ unsigned smem_u32(const void* p) {
    return (unsigned)__cvta_generic_to_shared((void*)p);
}
__device__ __forceinline__ void cp_async16(unsigned dst, const void* src) {
    asm volatile("cp.async.cg.shared.global [%0], [%1], 16;" :: "r"(dst), "l"(src));
}
__device__ __forceinline__ unsigned to_tf32(float f) {
    unsigned u; asm("cvt.rna.tf32.f32 %0, %1;" : "=r"(u) : "f"(f)); return u;
}
// FFMA-only exp(x) for x in [-16, 16] (no MUFU)
__device__ __forceinline__ float fast_exp(float x) {
    float t = x * 1.4426950408889634f;          // log2(e)
    float fi = floorf(t);
    float f = t - fi;
    float p = 1.5403530393381606e-4f;
    p = fmaf(p, f, 1.3333558146428443e-3f);
    p = fmaf(p, f, 9.618129107628477e-3f);
    p = fmaf(p, f, 5.550410866482158e-2f);
    p = fmaf(p, f, 2.402265069591007e-1f);
    p = fmaf(p, f, 6.931471805599453e-1f);
    p = fmaf(p, f, 1.0f);
    int ei = (int)fi;
    return __int_as_float((ei + 127) << 23) * p;
}
#define STS128(a, r0, r1, r2, r3) asm volatile("st.shared.v4.b32 [%0], {%1,%2,%3,%4};" :: "r"(a), "r"(r0), "r"(r1), "r"(r2), "r"(r3) : "memory")

// ---------------------------------------------------------------
// Kernel 1: global average pool. one block per (b,c)
// ---------------------------------------------------------------
__global__ void pool_kernel(const float* __restrict__ x) {
    __shared__ float red[256];
    int bc = blockIdx.x;
    const float* p = x + (size_t)bc * HWSZ;
    float s = 0.f;
    for (int i = threadIdx.x; i < HWSZ; i += 256) s += p[i];
    red[threadIdx.x] = s;
    __syncthreads();
    for (int off = 128; off > 0; off >>= 1) {
        if (threadIdx.x < off) red[threadIdx.x] += red[threadIdx.x + off];
        __syncthreads();
    }
    if (threadIdx.x == 0) g_pooled[bc] = red[0] * (1.0f / (float)HWSZ);
}

// ---------------------------------------------------------------
// Kernel 2: FCs. one block per b
// ---------------------------------------------------------------
__global__ void fc_kernel(const float* __restrict__ fc1,
                          const float* __restrict__ fc2,
                          const float* __restrict__ fc2b) {
    __shared__ float ps[CC];
    __shared__ float hs[CC];
    int b = blockIdx.x, tid = threadIdx.x;
    ps[tid] = g_pooled[b*CC + tid];
    __syncthreads();
    {
        const float* r1 = fc1 + (size_t)tid * CC;
        float a = 0.f;
        #pragma unroll 8
        for (int j = 0; j < CC; j++) a = fmaf(ps[j], r1[j], a);
        hs[tid] = fmaxf(a, 0.f);
    }
    __syncthreads();
    #pragma unroll
    for (int m4 = 0; m4 < 4; m4++) {
        int m = m4*CC + tid;                        // m = c*4 + t
        const float* r2 = fc2 + (size_t)m * CC;
        float s = fc2b[m];
        #pragma unroll 8
        for (int j = 0; j < CC; j++) s = fmaf(hs[j], r2[j], s);
        g_kern[b*CC*4 + m] = s;
    }
}

// ---------------------------------------------------------------
// Kernel 3: tf32 A images, quad per thread, FMA-exp + batched rcp.
//   g_wA[(b*2+og)][s][o_local][kk 0..35 (32 data + 4 pad)]
//   A[o][k] = sigmoid(sum_t kern[b,c,t]*cog[o,t,r9]) * weight[o,c,r9], k=c*9+r9
// ---------------------------------------------------------------
__global__ void dynw_kernel(const float* __restrict__ cog,
                            const float* __restrict__ weight) {
    int idx = blockIdx.x * 256 + threadIdx.x;   // < 64*72*128*9
    int q   = idx % 9;
    int o   = (idx / 9) % 128;
    int s   = (idx / (9*128)) % NSTG;
    int img = idx / (9*128*NSTG);
    int og = img & 1, b = img >> 1;
    int o_g = og*128 + o;

    unsigned* dst = g_wA + ((size_t)(img*NSTG + s)*128 + o)*APAD + q*4;

    if (q == 8) {   // pad floats 32..35 (never read by MMA, zero for safety)
        asm volatile("st.global.v4.u32 [%0], {%1,%1,%1,%1};" :: "l"(dst), "r"(0u) : "memory");
        return;
    }

    const float* cg = cog + (size_t)o_g * 36;
    float d[4], wv[4];
    #pragma unroll
    for (int u = 0; u < 4; u++) {
        int k = s*KST + q*4 + u;
        int c = k / 9, r9 = k - c*9;
        const float4 kv = *(const float4*)(g_kern + ((size_t)b*CC + c)*4);
        float sa = kv.x*cg[r9] + kv.y*cg[9+r9] + kv.z*cg[18+r9] + kv.w*cg[27+r9];
        sa = fminf(fmaxf(sa, -15.f), 15.f);
        d[u]  = 1.0f + fast_exp(-sa);
        wv[u] = weight[((size_t)o_g*CC + c)*9 + r9];
    }
    float p01 = d[0]*d[1], p23 = d[2]*d[3];
    float P = p01 * p23;
    float rp; asm("rcp.approx.f32 %0, %1;" : "=f"(rp) : "f"(P));
    unsigned v0 = to_tf32(wv[0] * (rp*d[1]*p23));
    unsigned v1 = to_tf32(wv[1] * (rp*d[0]*p23));
    unsigned v2 = to_tf32(wv[2] * (rp*p01*d[3]));
    unsigned v3 = to_tf32(wv[3] * (rp*p01*d[2]));
    asm volatile("st.global.v4.u32 [%0], {%1,%2,%3,%4};"
                 :: "l"(dst), "r"(v0), "r"(v1), "r"(v2), "r"(v3) : "memory");
}

// ---------------------------------------------------------------
// Kernel 4: TF32 mma.sync implicit-GEMM conv, LDG-prefetched im2col.
// Block (tile, og, b): D[128 o][112 px(2 rows x 56)] = A[128][2304] * B[112][2304]^T
// 8 warps = 4(M) x 2(N); warp tile 32 o x 56 px; mma m16n8k8.
// ---------------------------------------------------------------
__global__ __launch_bounds__(256, 2)
void conv_kernel(const float* __restrict__ x, float* __restrict__ out) {
    extern __shared__ __align__(16) float dsm[];
    float* As = dsm;                      // [2][A_FLOATS]
    float* Bs = dsm + 2*A_FLOATS;         // [2][B_FLOATS]

    const int tid  = threadIdx.x;
    const int lane = tid & 31;
    const int wid  = tid >> 5;
    const int warpM = wid & 3;
    const int warpN = wid >> 2;
    const int tile = blockIdx.x, og = blockIdx.y, b = blockIdx.z;
    const int h0 = tile * 2;

    const float* xb = x + (size_t)b * CC * HWSZ;
    const uint4* gA = (const uint4*)g_wA + (size_t)((b*2 + og) * NSTG) * A_CHUNKS;

    // B-build thread mapping (224 active): px = tid%112, half = tid/112
    const int pxid = tid % 112;
    const int half = tid / 112;
    const int rr = pxid / 56, cw = pxid % 56;
    const int ghb = h0 + rr - 1, gwb = cw - 1;
    const bool bact = (half < 2);
    const int kk0 = half * 16;

    float acc[2][7][4];
    #pragma unroll
    for (int m = 0; m < 2; m++)
        #pragma unroll
        for (int n = 0; n < 7; n++)
            #pragma unroll
            for (int q = 0; q < 4; q++) acc[m][n][q] = 0.f;

    const int aoff = (warpM*32 + (lane >> 2))*APAD + (lane & 3);
    const int boff = (warpN*56 + (lane >> 2))*APAD + (lane & 3);

    #define LOAD_A(S, BUF)                                                       \
    {                                                                            \
        const uint4* src_ = gA + (size_t)(S) * A_CHUNKS;                         \
        unsigned dst_ = smem_u32(As + (BUF) * A_FLOATS);                         \
        _Pragma("unroll")                                                        \
        for (int i_ = 0; i_ < 5; i_++) {                                         \
            int ch_ = tid + i_ * 256;                                            \
            if (ch_ < A_CHUNKS) cp_async16(dst_ + ch_*16, src_ + ch_);           \
        }                                                                        \
        asm volatile("cp.async.commit_group;");                                  \
    }

    // ---- prologue: direct build of B(0), async A(0) ----
    LOAD_A(0, 0);
    if (bact) {
        unsigned base_ = smem_u32(Bs + pxid*APAD + kk0);
        #pragma unroll
        for (int g_ = 0; g_ < 4; g_++) {
            unsigned vv_[4];
            #pragma unroll
            for (int u_ = 0; u_ < 4; u_++) {
                int k_ = kk0 + g_*4 + u_;
                int c_ = k_ / 9, r9_ = k_ - c_*9;
                int i3_ = r9_ / 3, j3_ = r9_ - i3_*3;
                int gh_ = ghb + i3_, gw_ = gwb + j3_;
                float v_ = 0.f;
                if (gh_ >= 0 && gh_ < HH && gw_ >= 0 && gw_ < WW)
                    v_ = __ldg(xb + (size_t)c_ * HWSZ + gh_ * WW + gw_);
                vv_[u_] = to_tf32(v_);
            }
            STS128(base_ + g_*16, vv_[0], vv_[1], vv_[2], vv_[3]);
        }
    }
    asm volatile("cp.async.wait_group 0;");
    __syncthreads();

    for (int s = 0; s < NSTG; s++) {
        const int p = s & 1;

        // ---- issue next-stage loads (latency hidden behind MMA below) ----
        if (s + 1 < NSTG) LOAD_A(s + 1, p ^ 1);
        float vreg[16];
        if (bact && (s + 1 < NSTG)) {
            #pragma unroll
            for (int u = 0; u < 16; u++) {
                int k_ = (s + 1)*KST + kk0 + u;
                int c_ = k_ / 9, r9_ = k_ - c_*9;
                int i3_ = r9_ / 3, j3_ = r9_ - i3_*3;
                int gh_ = ghb + i3_, gw_ = gwb + j3_;
                bool ok = (gh_ >= 0) && (gh_ < HH) && (gw_ >= 0) && (gw_ < WW);
                vreg[u] = ok ? __ldg(xb + (size_t)c_ * HWSZ + gh_ * WW + gw_) : 0.f;
            }
        }

        // ---- MMA on stage s ----
        const unsigned* Ap = (const unsigned*)(As + p * A_FLOATS);
        const unsigned* Bp = (const unsigned*)(Bs + p * B_FLOATS);
        #pragma unroll
        for (int ks = 0; ks < 4; ks++) {
            unsigned af[2][4], bf[7][2];
            #pragma unroll
            for (int m = 0; m < 2; m++) {
                const unsigned* ap = Ap + aoff + m*16*APAD + ks*8;
                af[m][0] = ap[0];
                af[m][1] = ap[8*APAD];
                af[m][2] = ap[4];
                af[m][3] = ap[8*APAD + 4];
            }
            #pragma unroll
            for (int n = 0; n < 7; n++) {
                const unsigned* bp = Bp + boff + n*8*APAD + ks*8;
                bf[n][0] = bp[0];
                bf[n][1] = bp[4];
            }
            #pragma unroll
            for (int m = 0; m < 2; m++)
                #pragma unroll
                for (int n = 0; n < 7; n++)
                    asm volatile(
                        "mma.sync.aligned.m16n8k8.row.col.f32.tf32.tf32.f32 "
                        "{%0,%1,%2,%3}, {%4,%5,%6,%7}, {%8,%9}, {%0,%1,%2,%3};"
                        : "+f"(acc[m][n][0]), "+f"(acc[m][n][1]),
                          "+f"(acc[m][n][2]), "+f"(acc[m][n][3])
                        : "r"(af[m][0]), "r"(af[m][1]), "r"(af[m][2]), "r"(af[m][3]),
                          "r"(bf[n][0]), "r"(bf[n][1]));
        }

        // ---- commit prefetched B values to the other buffer ----
        if (bact && (s + 1 < NSTG)) {
            unsigned base_ = smem_u32(Bs + (p ^ 1)*B_FLOATS + pxid*APAD + kk0);
            #pragma unroll
            for (int g_ = 0; g_ < 4; g_++)
                STS128(base_ + g_*16,
                       to_tf32(vreg[g_*4+0]), to_tf32(vreg[g_*4+1]),
                       to_tf32(vreg[g_*4+2]), to_tf32(vreg[g_*4+3]));
        }
        asm volatile("cp.async.wait_group 0;");
        __syncthreads();
    }
    #undef LOAD_A

    // ---- epilogue: fragments -> gmem (all px of a warp share one h row) ----
    const int h = h0 + warpN;
    const int wbase = (lane & 3) * 2;
    #pragma unroll
    for (int m = 0; m < 2; m++) {
        int o = og*128 + warpM*32 + m*16 + (lane >> 2);
        float* r0 = out + ((size_t)b*OO + o)*HWSZ + h*WW;
        float* r1 = out + ((size_t)b*OO + o + 8)*HWSZ + h*WW;
        #pragma unroll
        for (int n = 0; n < 7; n++) {
            int w = n*8 + wbase;
            *(float2*)(r0 + w) = make_float2(acc[m][n][0], acc[m][n][1]);
            *(float2*)(r1 + w) = make_float2(acc[m][n][2], acc[m][n][3]);
        }
    }
}

// ---------------------------------------------------------------
extern "C" void kernel_launch(void* const* d_in, const int* in_sizes, int n_in,
                              void* d_out, int out_size) {
    const float* x      = (const float*)d_in[0];
    const float* fc1_w  = (const float*)d_in[1];
    const float* fc2_w  = (const float*)d_in[2];
    const float* fc2_b  = (const float*)d_in[3];
    const float* cog_w  = (const float*)d_in[4];
    const float* weight = (const float*)d_in[5];
    float* out = (float*)d_out;

    cudaFuncSetAttribute(conv_kernel, cudaFuncAttributeMaxDynamicSharedMemorySize, SMEM_CONV);

    pool_kernel<<<BB*CC, 256>>>(x);
    fc_kernel<<<BB, 256>>>(fc1_w, fc2_w, fc2_b);
    {
        int total = BB*2*NSTG*128*9;       // 5,308,416 threads (quad each)
        dynw_kernel<<<total/256, 256>>>(cog_w, weight);
    }
    {
        dim3 grid(28, 2, BB);
        conv_kernel<<<grid, 256, SMEM_CONV>>>(x, out);
    }
}

// round 10
// speedup vs baseline: 2.1109x; 1.0115x over previous
#include <cuda_runtime.h>
#include <cuda_bf16.h>
#include <cstdint>
#include <cstddef>
#include <math.h>

#define BB 32
#define CC 256
#define OO 256
#define HH 56
#define WW 56
#define HWSZ 3136
#define KCH 4              // channels per stage
#define NST2 64            // stages (256/4)
#define S44 44             // 36 data + 4 zero + 4 pad floats per row
#define A_FL (128*S44)     // 5632 floats
#define B_FL (112*S44)     // 4928 floats
#define A_BYTES (A_FL*4)   // 22528
#define B_BYTES (B_FL*4)   // 19712
#define A_CH (A_BYTES/16)  // 1408 16B chunks
#define SMEM_CONV (2*(A_BYTES+B_BYTES))   // 84480 B

// ---- scratch ----
__device__ float g_pooled[BB*CC];
__device__ float g_kern[BB*CC*4];
__device__ unsigned g_wA[(size_t)BB*2*NST2*128*S44];   // tf32 A images, ~92MB

// ---- helpers ----
__device__ __forceinline__ unsigned smem_u32(const void* p) {
    return (unsigned)__cvta_generic_to_shared((void*)p);
}
__device__ __forceinline__ void cp_async16(unsigned dst, const void* src) {
    asm volatile("cp.async.cg.shared.global [%0], [%1], 16;" :: "r"(dst), "l"(src));
}
__device__ __forceinline__ void cp_async4_z(unsigned dst, const void* src, int src_sz) {
    asm volatile("cp.async.ca.shared.global [%0], [%1], 4, %2;" :: "r"(dst), "l"(src), "r"(src_sz));
}
__device__ __forceinline__ unsigned to_tf32(float f) {
    unsigned u; asm("cvt.rna.tf32.f32 %0, %1;" : "=r"(u) : "f"(f)); return u;
}
// FFMA-only exp(x) for x in [-16, 16] (no MUFU)
__device__ __forceinline__ float fast_exp(float x) {
    float t = x * 1.4426950408889634f;          // log2(e)
    float fi = floorf(t);
    float f = t - fi;
    float p = 1.5403530393381606e-4f;
    p = fmaf(p, f, 1.3333558146428443e-3f);
    p = fmaf(p, f, 9.618129107628477e-3f);
    p = fmaf(p, f, 5.550410866482158e-2f);
    p = fmaf(p, f, 2.402265069591007e-1f);
    p = fmaf(p, f, 6.931471805599453e-1f);
    p = fmaf(p, f, 1.0f);
    int ei = (int)fi;
    return __int_as_float((ei + 127) << 23) * p;
}
#define STS128(a, r0, r1, r2, r3) asm volatile("st.shared.v4.b32 [%0], {%1,%2,%3,%4};" :: "r"(a), "r"(r0), "r"(r1), "r"(r2), "r"(r3) : "memory")
#define STG128(a, r0, r1, r2, r3) asm volatile("st.global.v4.u32 [%0], {%1,%2,%3,%4};" :: "l"(a), "r"(r0), "r"(r1), "r"(r2), "r"(r3) : "memory")

// ---------------------------------------------------------------
// Kernel 1: global average pool. one block per (b,c)
// ---------------------------------------------------------------
__global__ void pool_kernel(const float* __restrict__ x) {
    __shared__ float red[256];
    int bc = blockIdx.x;
    const float* p = x + (size_t)bc * HWSZ;
    float s = 0.f;
    for (int i = threadIdx.x; i < HWSZ; i += 256) s += p[i];
    red[threadIdx.x] = s;
    __syncthreads();
    for (int off = 128; off > 0; off >>= 1) {
        if (threadIdx.x < off) red[threadIdx.x] += red[threadIdx.x + off];
        __syncthreads();
    }
    if (threadIdx.x == 0) g_pooled[bc] = red[0] * (1.0f / (float)HWSZ);
}

// ---------------------------------------------------------------
// Kernel 2: FCs. one block per b
// ---------------------------------------------------------------
__global__ void fc_kernel(const float* __restrict__ fc1,
                          const float* __restrict__ fc2,
                          const float* __restrict__ fc2b) {
    __shared__ float ps[CC];
    __shared__ float hs[CC];
    int b = blockIdx.x, tid = threadIdx.x;
    ps[tid] = g_pooled[b*CC + tid];
    __syncthreads();
    {
        const float* r1 = fc1 + (size_t)tid * CC;
        float a = 0.f;
        #pragma unroll 8
        for (int j = 0; j < CC; j++) a = fmaf(ps[j], r1[j], a);
        hs[tid] = fmaxf(a, 0.f);
    }
    __syncthreads();
    #pragma unroll
    for (int m4 = 0; m4 < 4; m4++) {
        int m = m4*CC + tid;                        // m = c*4 + t
        const float* r2 = fc2 + (size_t)m * CC;
        float s = fc2b[m];
        #pragma unroll 8
        for (int j = 0; j < CC; j++) s = fmaf(hs[j], r2[j], s);
        g_kern[b*CC*4 + m] = s;
    }
}

// ---------------------------------------------------------------
// Kernel 3: tf32 A images, one thread per 44-float row.
//   layout: g_wA[img(=b*2+og)][s][o][44], kk = ci*9 + r9 (ci=0..3, r9=0..8)
//   A[kk] = sigmoid(sum_t kern[b,c0+ci,t]*cog[o_g,t,r9]) * weight[o_g,c0+ci,r9]
//   kk 36..43 = 0.
// idx bits: img[18:13] s[12:7] o[6:0]  (all pow-2, no divisions)
// ---------------------------------------------------------------
__global__ void dynw_kernel(const float* __restrict__ cog,
                            const float* __restrict__ weight) {
    int idx = blockIdx.x * 256 + threadIdx.x;   // < 2^19
    int o   = idx & 127;
    int s   = (idx >> 7) & 63;
    int img = idx >> 13;
    int og = img & 1, b = img >> 1;
    int o_g = og*128 + o;
    int c0 = s*KCH;

    const float*  cg   = cog + (size_t)o_g * 36;
    const float*  wrow = weight + ((size_t)o_g*CC + c0)*9;   // 36 consecutive
    const float4* kvp  = (const float4*)(g_kern + ((size_t)b*CC + c0)*4);

    float dd[36], wv[36];
    #pragma unroll
    for (int kk = 0; kk < 36; kk++) {
        int ci = kk/9, r9 = kk%9;               // compile-time
        float4 kv = kvp[ci];
        float sa = kv.x*cg[r9] + kv.y*cg[9+r9] + kv.z*cg[18+r9] + kv.w*cg[27+r9];
        sa = fminf(fmaxf(sa, -15.f), 15.f);
        dd[kk] = 1.0f + fast_exp(-sa);
        wv[kk] = wrow[kk];
    }
    unsigned* dst = g_wA + (size_t)idx * S44;
    #pragma unroll
    for (int g = 0; g < 9; g++) {
        float d0 = dd[g*4], d1 = dd[g*4+1], d2 = dd[g*4+2], d3 = dd[g*4+3];
        float p01 = d0*d1, p23 = d2*d3;
        float P = p01 * p23;
        float rp; asm("rcp.approx.f32 %0, %1;" : "=f"(rp) : "f"(P));
        unsigned v0 = to_tf32(wv[g*4+0] * (rp*d1*p23));
        unsigned v1 = to_tf32(wv[g*4+1] * (rp*d0*p23));
        unsigned v2 = to_tf32(wv[g*4+2] * (rp*p01*d3));
        unsigned v3 = to_tf32(wv[g*4+3] * (rp*p01*d2));
        STG128(dst + g*4, v0, v1, v2, v3);
    }
    STG128(dst + 36, 0u, 0u, 0u, 0u);
    STG128(dst + 40, 0u, 0u, 0u, 0u);
}

// ---------------------------------------------------------------
// Kernel 4: TF32 mma.sync implicit-GEMM conv, stage = 4 channels x 9 taps.
// Block (tile, og, b): D[128 o][112 px(2 rows x 56)]; 64 stages of 40 k (5 ksteps).
// B fed by cp.async 4B zero-fill with prologue-constant offsets.
// 8 warps = 4(M) x 2(N); warp tile 32 o x 56 px; mma m16n8k8.
// ---------------------------------------------------------------
__global__ __launch_bounds__(256, 2)
void conv_kernel(const float* __restrict__ x, float* __restrict__ out) {
    extern __shared__ __align__(16) float dsm[];
    float* As = dsm;                      // [2][A_FL]
    float* Bs = dsm + 2*A_FL;             // [2][B_FL]

    const int tid  = threadIdx.x;
    const int lane = tid & 31;
    const int wid  = tid >> 5;
    const int warpM = wid & 3;
    const int warpN = wid >> 2;
    const int tile = blockIdx.x, og = blockIdx.y, b = blockIdx.z;
    const int h0 = tile * 2;

    const float* xb = x + (size_t)b * CC * HWSZ;
    const uint4* gA = (const uint4*)g_wA + (size_t)((b*2 + og) * NST2) * A_CH;

    // ---- B im2col mapping: px = tid/2, half = tid&1 covers kk half*18..+17 ----
    const int px = tid >> 1;
    const int half = tid & 1;
    const bool bact = (tid < 224);
    const int rr = px / 56, cw = px % 56;
    const int ghb = h0 + rr - 1, gwb = cw - 1;

    int goff[18];
    unsigned vmask = 0;
    #pragma unroll
    for (int u = 0; u < 18; u++) {
        int ci = 2*half + (u/9);         // u/9, u%9 compile-time
        int r9 = u % 9;
        int i3 = r9 / 3, j3 = r9 % 3;
        int gh = ghb + i3, gw = gwb + j3;
        bool ok = (gh >= 0) && (gh < HH) && (gw >= 0) && (gw < WW);
        goff[u] = ok ? (ci*HWSZ + gh*WW + gw) : 0;
        vmask |= (ok ? 1u : 0u) << u;
    }
    const unsigned dstb_off = (unsigned)(px*(S44*4) + half*72);   // byte offset in B buf

    float acc[2][7][4];
    #pragma unroll
    for (int m = 0; m < 2; m++)
        #pragma unroll
        for (int n = 0; n < 7; n++)
            #pragma unroll
            for (int q = 0; q < 4; q++) acc[m][n][q] = 0.f;

    const int aoff = (warpM*32 + (lane >> 2))*S44 + (lane & 3);
    const int boff = (warpN*56 + (lane >> 2))*S44 + (lane & 3);

    // ---- zero B lanes kk36..39 once (never overwritten; avoids 0*garbage NaN) ----
    if (tid < 112) {
        STS128(smem_u32(Bs + 0*B_FL + tid*S44 + 36), 0u, 0u, 0u, 0u);
        STS128(smem_u32(Bs + 1*B_FL + tid*S44 + 36), 0u, 0u, 0u, 0u);
    }
    __syncthreads();

    #define ISSUE(S, BUF)                                                        \
    {                                                                            \
        const uint4* srcA_ = gA + (size_t)(S) * A_CH;                            \
        unsigned dA_ = smem_u32(As) + (BUF)*A_BYTES;                             \
        _Pragma("unroll")                                                        \
        for (int i_ = 0; i_ < 6; i_++) {                                         \
            int ch_ = tid + i_ * 256;                                            \
            if (ch_ < A_CH) cp_async16(dA_ + ch_*16, srcA_ + ch_);               \
        }                                                                        \
        if (bact) {                                                              \
            const float* sb_ = xb + (size_t)(S) * (KCH*HWSZ);                    \
            unsigned dB_ = smem_u32(Bs) + (BUF)*B_BYTES + dstb_off;              \
            _Pragma("unroll")                                                    \
            for (int u_ = 0; u_ < 18; u_++) {                                    \
                int sz_ = ((vmask >> u_) & 1) * 4;                               \
                cp_async4_z(dB_ + u_*4, sb_ + goff[u_], sz_);                    \
            }                                                                    \
        }                                                                        \
        asm volatile("cp.async.commit_group;");                                  \
    }

    // prologue
    ISSUE(0, 0);
    asm volatile("cp.async.wait_group 0;");
    __syncthreads();

    for (int s = 0; s < NST2; s++) {
        const int p = s & 1;
        if (s + 1 < NST2) ISSUE(s + 1, p ^ 1);

        const unsigned* Ap = (const unsigned*)(As + p * A_FL);
        const unsigned* Bp = (const unsigned*)(Bs + p * B_FL);
        #pragma unroll
        for (int ks = 0; ks < 5; ks++) {
            unsigned af[2][4], bf[7][2];
            #pragma unroll
            for (int m = 0; m < 2; m++) {
                const unsigned* ap = Ap + aoff + m*16*S44 + ks*8;
                af[m][0] = ap[0];
                af[m][1] = ap[8*S44];
                af[m][2] = ap[4];
                af[m][3] = ap[8*S44 + 4];
            }
            #pragma unroll
            for (int n = 0; n < 7; n++) {
                const unsigned* bp = Bp + boff + n*8*S44 + ks*8;
                bf[n][0] = bp[0];
                bf[n][1] = bp[4];
            }
            #pragma unroll
            for (int m = 0; m < 2; m++)
                #pragma unroll
                for (int n = 0; n < 7; n++)
                    asm volatile(
                        "mma.sync.aligned.m16n8k8.row.col.f32.tf32.tf32.f32 "
                        "{%0,%1,%2,%3}, {%4,%5,%6,%7}, {%8,%9}, {%0,%1,%2,%3};"
                        : "+f"(acc[m][n][0]), "+f"(acc[m][n][1]),
                          "+f"(acc[m][n][2]), "+f"(acc[m][n][3])
                        : "r"(af[m][0]), "r"(af[m][1]), "r"(af[m][2]), "r"(af[m][3]),
                          "r"(bf[n][0]), "r"(bf[n][1]));
        }

        asm volatile("cp.async.wait_group 0;");
        __syncthreads();
    }
    #undef ISSUE

    // ---- epilogue: fragments -> gmem (all px of a warp share one h row) ----
    const int h = h0 + warpN;
    const int wbase = (lane & 3) * 2;
    #pragma unroll
    for (int m = 0; m < 2; m++) {
        int o = og*128 + warpM*32 + m*16 + (lane >> 2);
        float* r0 = out + ((size_t)b*OO + o)*HWSZ + h*WW;
        float* r1 = out + ((size_t)b*OO + o + 8)*HWSZ + h*WW;
        #pragma unroll
        for (int n = 0; n < 7; n++) {
            int w = n*8 + wbase;
            *(float2*)(r0 + w) = make_float2(acc[m][n][0], acc[m][n][1]);
            *(float2*)(r1 + w) = make_float2(acc[m][n][2], acc[m][n][3]);
        }
    }
}

// ---------------------------------------------------------------
extern "C" void kernel_launch(void* const* d_in, const int* in_sizes, int n_in,
                              void* d_out, int out_size) {
    const float* x      = (const float*)d_in[0];
    const float* fc1_w  = (const float*)d_in[1];
    const float* fc2_w  = (const float*)d_in[2];
    const float* fc2_b  = (const float*)d_in[3];
    const float* cog_w  = (const float*)d_in[4];
    const float* weight = (const float*)d_in[5];
    float* out = (float*)d_out;

    cudaFuncSetAttribute(conv_kernel, cudaFuncAttributeMaxDynamicSharedMemorySize, SMEM_CONV);

    pool_kernel<<<BB*CC, 256>>>(x);
    fc_kernel<<<BB, 256>>>(fc1_w, fc2_w, fc2_b);
    dynw_kernel<<<2048, 256>>>(cog_w, weight);   // 2^19 rows
    {
        dim3 grid(28, 2, BB);
        conv_kernel<<<grid, 256, SMEM_CONV>>>(x, out);
    }
}